// round 15
// baseline (speedup 1.0000x reference)
#include <cuda_runtime.h>
#include <cuda_fp16.h>
#include <cstdint>

#define NB 8
#define NTX 128
#define NTY 128
#define ND 512
#define NH 512
#define TYB 8

// Scratch (allocation-free rule: __device__ globals)
// tanh-precomputed f32 arrays: T = tanh(proj), V = Va * tanh(proj)
__device__ float g_TW[NB * NH * NTX];   // [b][h][tx]
__device__ float g_VW[NB * NH * NTX];
__device__ float g_TU[NB * NH * NTY];   // [b][h][ty]
__device__ float g_VU[NB * NH * NTY];

__device__ __forceinline__ void mma_f16(float d[4], const uint32_t a[4],
                                        const uint32_t b[2]) {
    asm volatile(
        "mma.sync.aligned.m16n8k16.row.col.f32.f16.f16.f32 "
        "{%0,%1,%2,%3}, {%4,%5,%6,%7}, {%8,%9}, {%0,%1,%2,%3};"
        : "+f"(d[0]), "+f"(d[1]), "+f"(d[2]), "+f"(d[3])
        : "r"(a[0]), "r"(a[1]), "r"(a[2]), "r"(a[3]), "r"(b[0]), "r"(b[1]));
}

__device__ __forceinline__ float tanh_f32(float x) {
    float y;
    asm("tanh.approx.f32 %0, %1;" : "=f"(y) : "f"(x));
    return y;
}

__device__ __forceinline__ float rcp_f32(float x) {
    float y;
    asm("rcp.approx.f32 %0, %1;" : "=f"(y) : "f"(x));
    return y;
}

// ---------------------------------------------------------------------------
// Kernel 1 (fp16 HMMA, R14 mainloop): computes proj = A@W + bias, then the
// epilogue applies tanh and writes T = tanh(proj), V = Va*tanh(proj) (f32,
// transposed [h][t]).
// ---------------------------------------------------------------------------
__global__ void __launch_bounds__(256)
bahdanau_gemm_tc(const float* __restrict__ Ctx, const float* __restrict__ X,
                 const float* __restrict__ Wa, const float* __restrict__ bWa,
                 const float* __restrict__ Ua, const float* __restrict__ bUa,
                 const float* __restrict__ Va)
{
    const int which = blockIdx.z >> 3;       // 0: Wc, 1: Ux
    const int b     = blockIdx.z & 7;
    const float* A    = (which ? X  : Ctx) + b * NTX * ND;   // [128][512]
    const float* W    =  which ? Ua : Wa;                    // [512][512]
    const float* bias =  which ? bUa : bWa;
    float* Tout = (which ? g_TU : g_TW) + (size_t)b * NH * NTX;  // [512][128]
    float* Vout = (which ? g_VU : g_VW) + (size_t)b * NH * NTX;

    const int h0 = blockIdx.x * 64;
    const int t0 = blockIdx.y * 64;

    // smem: As [64][40] halfs (5120 B), Bs [64][34] halfs (4352 B),
    // Sout [64][68] floats (17408 B) overlays both after the mainloop.
    __shared__ __align__(16) char smem_raw[17408];
    __half (*As)[40]   = reinterpret_cast<__half(*)[40]>(smem_raw);
    __half (*Bs)[34]   = reinterpret_cast<__half(*)[34]>(smem_raw + 5120);
    float (*Sout)[68]  = reinterpret_cast<float(*)[68]>(smem_raw);

    const int tid  = threadIdx.x;
    const int warp = tid >> 5, lane = tid & 31;
    const int wm = warp >> 2, wn = warp & 3;    // 2x4 warp grid
    const int gid = lane >> 2, tq = lane & 3;

    const int arow = tid >> 2, ak = (tid & 3) * 8;   // A: 64 t-rows x 32 k
    const int brow = tid >> 3, bh = (tid & 7) * 8;   // B: 32 k-rows x 64 h

    const float* Abase = A + (t0 + arow) * ND + ak;
    const float* Bbase = W + brow * NH + h0 + bh;

    float4 pa[2], pb[2];
#pragma unroll
    for (int i = 0; i < 2; i++) pa[i] = *(const float4*)(Abase + i * 4);
#pragma unroll
    for (int i = 0; i < 2; i++) pb[i] = *(const float4*)(Bbase + i * 4);

    float acc[2][2][4];
#pragma unroll
    for (int mt = 0; mt < 2; mt++)
#pragma unroll
        for (int nt = 0; nt < 2; nt++)
#pragma unroll
            for (int r = 0; r < 4; r++) acc[mt][nt][r] = 0.f;

#pragma unroll 1
    for (int kc = 0; kc < 16; kc++) {
        __syncthreads();
        {   // A tile: pack 8 fp32 -> 8 fp16 -> one 16B STS
            __half2 h2[4];
            h2[0] = __floats2half2_rn(pa[0].x, pa[0].y);
            h2[1] = __floats2half2_rn(pa[0].z, pa[0].w);
            h2[2] = __floats2half2_rn(pa[1].x, pa[1].y);
            h2[3] = __floats2half2_rn(pa[1].z, pa[1].w);
            *reinterpret_cast<uint4*>(&As[arow][ak]) =
                *reinterpret_cast<uint4*>(h2);
        }
        {   // B tile: transpose scatter — Bs[h][k]
            const float* pf = reinterpret_cast<const float*>(pb);
#pragma unroll
            for (int i = 0; i < 8; i++)
                Bs[bh + i][brow] = __float2half_rn(pf[i]);
        }
        __syncthreads();

        if (kc < 15) {   // prefetch next K chunk (overlaps mma)
            const float* an = Abase + (kc + 1) * 32;
            const float* bn = Bbase + (size_t)(kc + 1) * 32 * NH;
#pragma unroll
            for (int i = 0; i < 2; i++) pa[i] = *(const float4*)(an + i * 4);
#pragma unroll
            for (int i = 0; i < 2; i++) pb[i] = *(const float4*)(bn + i * 4);
        }

#pragma unroll
        for (int ks = 0; ks < 2; ks++) {
            const int kb = ks * 16;
            uint32_t af[2][4], bf[2][2];
#pragma unroll
            for (int mt = 0; mt < 2; mt++) {
                const int r = wm * 32 + mt * 16 + gid;
                af[mt][0] = *reinterpret_cast<const uint32_t*>(&As[r    ][kb + 2 * tq]);
                af[mt][1] = *reinterpret_cast<const uint32_t*>(&As[r + 8][kb + 2 * tq]);
                af[mt][2] = *reinterpret_cast<const uint32_t*>(&As[r    ][kb + 2 * tq + 8]);
                af[mt][3] = *reinterpret_cast<const uint32_t*>(&As[r + 8][kb + 2 * tq + 8]);
            }
#pragma unroll
            for (int nt = 0; nt < 2; nt++) {
                const int c = wn * 16 + nt * 8 + gid;
                bf[nt][0] = *reinterpret_cast<const uint32_t*>(&Bs[c][kb + 2 * tq]);
                bf[nt][1] = *reinterpret_cast<const uint32_t*>(&Bs[c][kb + 2 * tq + 8]);
            }
#pragma unroll
            for (int mt = 0; mt < 2; mt++)
#pragma unroll
                for (int nt = 0; nt < 2; nt++)
                    mma_f16(acc[mt][nt], af[mt], bf[nt]);
        }
    }
    __syncthreads();

    // Transpose via smem: Sout[n(h)][m(t)]
#pragma unroll
    for (int mt = 0; mt < 2; mt++)
#pragma unroll
        for (int nt = 0; nt < 2; nt++) {
            const int n = wn * 16 + nt * 8 + 2 * tq;
            const int m = wm * 32 + mt * 16 + gid;
            Sout[n    ][m    ] = acc[mt][nt][0];
            Sout[n + 1][m    ] = acc[mt][nt][1];
            Sout[n    ][m + 8] = acc[mt][nt][2];
            Sout[n + 1][m + 8] = acc[mt][nt][3];
        }
    __syncthreads();

    // Epilogue: bias + tanh -> T, Va*T -> V. 64 h-rows x 64 t; 16 t/thread.
    {
        const int row = tid >> 2;
        const int cg  = (tid & 3) * 16;
        const float bv = __ldg(&bias[h0 + row]);
        const float va = __ldg(&Va[h0 + row]);
        float tv[16], vv[16];
#pragma unroll
        for (int k = 0; k < 16; k++) {
            float t = tanh_f32(Sout[row][cg + k] + bv);
            tv[k] = t;
            vv[k] = va * t;
        }
        float* trow = Tout + (size_t)(h0 + row) * NTX + t0 + cg;
        float* vrow = Vout + (size_t)(h0 + row) * NTX + t0 + cg;
#pragma unroll
        for (int k = 0; k < 4; k++) {
            *reinterpret_cast<float4*>(trow + 4 * k) =
                *reinterpret_cast<float4*>(&tv[4 * k]);
            *reinterpret_cast<float4*>(vrow + 4 * k) =
                *reinterpret_cast<float4*>(&vv[4 * k]);
        }
    }
}

// ---------------------------------------------------------------------------
// Kernel 2: fused scores + softmax + cv + LayerNorm + residual.
// Phase 1 uses the tanh addition formula:
//   tanh(w+u) = (tw+tu)/(1+tw*tu);  Va*tanh(w+u) = (vw+vu) * rcp(1+tw*tu)
// -> MUFU.RCP (rt 8) instead of MUFU.TANH (elem rate 2x).
// 512 threads = 64 tx-pairs x 8 h-groups (64 h each).
// ---------------------------------------------------------------------------
__global__ void __launch_bounds__(512)
bahdanau_attn(const float* __restrict__ Ctx, const float* __restrict__ X,
              const float* __restrict__ gamma, const float* __restrict__ beta,
              float* __restrict__ out)
{
    const int b   = blockIdx.x >> 4;
    const int ty0 = (blockIdx.x & 15) * TYB;

    __shared__ __align__(16) float pool[8192];        // 32 KB
    __shared__ __align__(16) float attn_s[TYB][NTX];  //  4 KB
    float* tu_s = pool;          // [512][8] during phase 1
    float* vu_s = pool + 4096;   // [512][8] during phase 1
    // after phase 1, pool overlays part[8][TYB][NTX] (= 8192 floats)

    const int tid = threadIdx.x;

    // Stage tu/vu (one h per thread: 8 ty f32 = 2 x float4)
    {
        const float* tsrc = g_TU + ((size_t)(b * NH + tid)) * NTY + ty0;
        const float* vsrc = g_VU + ((size_t)(b * NH + tid)) * NTY + ty0;
        *reinterpret_cast<float4*>(&tu_s[tid * 8])     = *(const float4*)(tsrc);
        *reinterpret_cast<float4*>(&tu_s[tid * 8 + 4]) = *(const float4*)(tsrc + 4);
        *reinterpret_cast<float4*>(&vu_s[tid * 8])     = *(const float4*)(vsrc);
        *reinterpret_cast<float4*>(&vu_s[tid * 8 + 4]) = *(const float4*)(vsrc + 4);
    }
    __syncthreads();

    // ---- Phase 1: s[j][tx] = sum_h (vw+vu) * rcp(1 + tw*tu)
    {
        const int txp = tid & 63;        // tx pair: tx = 2txp, 2txp+1
        const int g   = tid >> 6;        // h-group: h in [g*64, g*64+64)

        float sacc[TYB][2];
#pragma unroll
        for (int j = 0; j < TYB; j++) { sacc[j][0] = 0.f; sacc[j][1] = 0.f; }

        const float2* twp = reinterpret_cast<const float2*>(
            g_TW + (size_t)(b * NH + g * 64) * NTX) + txp;     // h stride 64
        const float2* vwp = reinterpret_cast<const float2*>(
            g_VW + (size_t)(b * NH + g * 64) * NTX) + txp;

        float2 twr[4], vwr[4];
#pragma unroll
        for (int i = 0; i < 4; i++) {
            twr[i] = __ldg(twp + i * 64);
            vwr[i] = __ldg(vwp + i * 64);
        }

#pragma unroll 1
        for (int hh = 0; hh < 64; hh += 4) {
            float2 twn[4], vwn[4];
            const bool more = (hh + 4) < 64;
#pragma unroll
            for (int i = 0; i < 4; i++) {
                twn[i] = more ? __ldg(twp + (hh + 4 + i) * 64) : make_float2(0.f, 0.f);
                vwn[i] = more ? __ldg(vwp + (hh + 4 + i) * 64) : make_float2(0.f, 0.f);
            }

#pragma unroll
            for (int i = 0; i < 4; i++) {
                const int h = g * 64 + hh + i;
                const float twx = twr[i].x, twy = twr[i].y;
                const float vwx = vwr[i].x, vwy = vwr[i].y;
                float4 tu0 = *reinterpret_cast<const float4*>(&tu_s[h * 8]);
                float4 tu1 = *reinterpret_cast<const float4*>(&tu_s[h * 8 + 4]);
                float4 vu0 = *reinterpret_cast<const float4*>(&vu_s[h * 8]);
                float4 vu1 = *reinterpret_cast<const float4*>(&vu_s[h * 8 + 4]);
                const float* tu = reinterpret_cast<const float*>(&tu0);  // [0..3]
                const float* tub = reinterpret_cast<const float*>(&tu1); // [4..7]
                const float* vu = reinterpret_cast<const float*>(&vu0);
                const float* vub = reinterpret_cast<const float*>(&vu1);
#pragma unroll
                for (int j = 0; j < 4; j++) {
                    float t = tu[j], v = vu[j];
                    float d0 = fmaxf(fmaf(twx, t, 1.f), 1e-6f);
                    float d1 = fmaxf(fmaf(twy, t, 1.f), 1e-6f);
                    sacc[j][0] = fmaf(vwx + v, rcp_f32(d0), sacc[j][0]);
                    sacc[j][1] = fmaf(vwy + v, rcp_f32(d1), sacc[j][1]);
                }
#pragma unroll
                for (int j = 0; j < 4; j++) {
                    float t = tub[j], v = vub[j];
                    float d0 = fmaxf(fmaf(twx, t, 1.f), 1e-6f);
                    float d1 = fmaxf(fmaf(twy, t, 1.f), 1e-6f);
                    sacc[4 + j][0] = fmaf(vwx + v, rcp_f32(d0), sacc[4 + j][0]);
                    sacc[4 + j][1] = fmaf(vwy + v, rcp_f32(d1), sacc[4 + j][1]);
                }
            }
#pragma unroll
            for (int i = 0; i < 4; i++) { twr[i] = twn[i]; vwr[i] = vwn[i]; }
        }

        __syncthreads();   // all tu/vu reads done before part overlays pool
#pragma unroll
        for (int j = 0; j < TYB; j++)
            *reinterpret_cast<float2*>(&pool[(g * TYB + j) * NTX + 2 * txp]) =
                make_float2(sacc[j][0], sacc[j][1]);
    }
    __syncthreads();

    // ---- Phase 2: softmax over tx per ty row; warp j (j<8) handles row j.
    if (tid < 256) {
        const int j = tid >> 5, lane = tid & 31;
        float vals[4];
        float mx = -1e30f;
#pragma unroll
        for (int i = 0; i < 4; i++) {
            int t = lane + i * 32;
            float v = 0.f;
#pragma unroll
            for (int g = 0; g < 8; g++)
                v += pool[(g * TYB + j) * NTX + t];
            vals[i] = v;
            mx = fmaxf(mx, v);
        }
#pragma unroll
        for (int off = 16; off; off >>= 1)
            mx = fmaxf(mx, __shfl_xor_sync(0xffffffffu, mx, off));
        float sum = 0.f;
#pragma unroll
        for (int i = 0; i < 4; i++) {
            vals[i] = __expf(vals[i] - mx);
            sum += vals[i];
        }
#pragma unroll
        for (int off = 16; off; off >>= 1)
            sum += __shfl_xor_sync(0xffffffffu, sum, off);
        float inv = __frcp_rn(sum);
#pragma unroll
        for (int i = 0; i < 4; i++)
            attn_s[j][lane + i * 32] = vals[i] * inv;
    }
    __syncthreads();

    // ---- Phase 3: cv[j][d] = sum_tx attn[j][tx] * context[b][tx][d]
    {
        const int g2 = tid >> 8;
        const int l  = tid & 255;
        const int d0 = l * 2;
        float acc[TYB][2];
#pragma unroll
        for (int j = 0; j < TYB; j++) { acc[j][0] = 0.f; acc[j][1] = 0.f; }
        const float* cbase = Ctx + (size_t)b * NTX * ND + (size_t)(g2 * 64) * ND + d0;
#pragma unroll 1
        for (int t = 0; t < 64; t += 8) {
            float2 c[8];
#pragma unroll
            for (int i = 0; i < 8; i++)
                c[i] = *reinterpret_cast<const float2*>(cbase + (size_t)(t + i) * ND);
#pragma unroll
            for (int i = 0; i < 8; i++) {
                const int tt = g2 * 64 + t + i;
#pragma unroll
                for (int j = 0; j < TYB; j++) {
                    float a = attn_s[j][tt];
                    acc[j][0] += a * c[i].x;
                    acc[j][1] += a * c[i].y;
                }
            }
        }
        __syncthreads();   // partial-score reads done before cv overlay
#pragma unroll
        for (int j = 0; j < TYB; j++) {
            pool[g2 * 4096 + j * 512 + d0]     = acc[j][0];  // cvp overlay
            pool[g2 * 4096 + j * 512 + d0 + 1] = acc[j][1];
        }
    }
    __syncthreads();

    // ---- Phase 4: LayerNorm + residual. Warp j (j<8) handles row j.
    if (tid < 256) {
        const int j = tid >> 5, lane = tid & 31;
        float vals[16];
        float sum = 0.f;
#pragma unroll
        for (int i = 0; i < 16; i++) {
            int d = i * 32 + lane;
            vals[i] = pool[j * 512 + d] + pool[4096 + j * 512 + d];
            sum += vals[i];
        }
#pragma unroll
        for (int off = 16; off; off >>= 1)
            sum += __shfl_xor_sync(0xffffffffu, sum, off);
        const float mean = sum * (1.0f / ND);
        float vsum = 0.f;
#pragma unroll
        for (int i = 0; i < 16; i++) {
            float dlt = vals[i] - mean;
            vsum += dlt * dlt;
        }
#pragma unroll
        for (int off = 16; off; off >>= 1)
            vsum += __shfl_xor_sync(0xffffffffu, vsum, off);
        const float scale = rsqrtf(vsum * (1.0f / ND) + 1e-3f);

        const int ty = ty0 + j;
        const float* xr = X + ((size_t)b * NTY + ty) * ND;
        float* orow = out + ((size_t)b * NTY + ty) * ND;
#pragma unroll
        for (int i = 0; i < 16; i++) {
            int d = i * 32 + lane;
            orow[d] = (vals[i] - mean) * scale * gamma[d] + beta[d] + xr[d];
        }
    }
}

// ---------------------------------------------------------------------------
extern "C" void kernel_launch(void* const* d_in, const int* in_sizes, int n_in,
                              void* d_out, int out_size)
{
    const float* ctx   = (const float*)d_in[0];
    const float* x     = (const float*)d_in[1];
    const float* Wa    = (const float*)d_in[2];
    const float* bWa   = (const float*)d_in[3];
    const float* Ua    = (const float*)d_in[4];
    const float* bUa   = (const float*)d_in[5];
    const float* Va    = (const float*)d_in[6];
    // d_in[7] = bVa: scalar added to scores; cancels exactly in softmax.
    const float* gamma = (const float*)d_in[8];
    const float* beta  = (const float*)d_in[9];
    float* out = (float*)d_out;

    dim3 g1(NH / 64, NTX / 64, NB * 2);   // (8, 2, 16) = 256 blocks
    bahdanau_gemm_tc<<<g1, 256>>>(ctx, x, Wa, bWa, Ua, bUa, Va);

    bahdanau_attn<<<NB * (NTY / TYB), 512>>>(ctx, x, gamma, beta, out);
}

// round 16
// speedup vs baseline: 1.4197x; 1.4197x over previous
#include <cuda_runtime.h>
#include <cuda_fp16.h>
#include <cstdint>

#define NB 8
#define NTX 128
#define NTY 128
#define ND 512
#define NH 512
#define TYB 8

// Scratch (allocation-free rule: __device__ globals) — fp16
__device__ __half g_WcT[NB * NH * NTX];   // [b][h][tx]
__device__ __half g_UxT[NB * NH * NTY];   // [b][h][ty]

__device__ __forceinline__ void mma_f16(float d[4], const uint32_t a[4],
                                        const uint32_t b[2]) {
    asm volatile(
        "mma.sync.aligned.m16n8k16.row.col.f32.f16.f16.f32 "
        "{%0,%1,%2,%3}, {%4,%5,%6,%7}, {%8,%9}, {%0,%1,%2,%3};"
        : "+f"(d[0]), "+f"(d[1]), "+f"(d[2]), "+f"(d[3])
        : "r"(a[0]), "r"(a[1]), "r"(a[2]), "r"(a[3]), "r"(b[0]), "r"(b[1]));
}

__device__ __forceinline__ __half2 htanh2(__half2 x) {
    uint32_t u = *reinterpret_cast<uint32_t*>(&x), t;
    asm("tanh.approx.f16x2 %0, %1;" : "=r"(t) : "r"(u));
    return *reinterpret_cast<__half2*>(&t);
}

// ---------------------------------------------------------------------------
// Kernel 1 (fp16 HMMA, double-buffered smem): OutT = A @ W + bias, fp16
// transposed. Tile 64(t) x 64(h), 256 threads (2x4 warps), K chunks of 32.
// Chunk c lives in smem buffer c&1: STS(c+1) overlaps mma(c); 1 barrier/chunk.
// ---------------------------------------------------------------------------
__global__ void __launch_bounds__(256)
bahdanau_gemm_tc(const float* __restrict__ Ctx, const float* __restrict__ X,
                 const float* __restrict__ Wa, const float* __restrict__ bWa,
                 const float* __restrict__ Ua, const float* __restrict__ bUa)
{
    const int which = blockIdx.z >> 3;       // 0: Wc, 1: Ux
    const int b     = blockIdx.z & 7;
    const float* A    = (which ? X  : Ctx) + b * NTX * ND;   // [128][512]
    const float* W    =  which ? Ua : Wa;                    // [512][512]
    const float* bias =  which ? bUa : bWa;
    __half* OutT = (which ? g_UxT : g_WcT) + (size_t)b * NH * NTX;  // [512][128]

    const int h0 = blockIdx.x * 64;
    const int t0 = blockIdx.y * 64;

    // smem: As[2] 64x40 halfs (2x5120 B), Bs[2] 64x34 halfs (2x4352 B) = 18944 B
    // Sout [64][68] f32 (17408 B) overlays everything after the mainloop.
    __shared__ __align__(16) char smem_raw[18944];
    __half* AsBuf = reinterpret_cast<__half*>(smem_raw);            // + buf*2560
    __half* BsBuf = reinterpret_cast<__half*>(smem_raw + 10240);    // + buf*2176
    float (*Sout)[68] = reinterpret_cast<float(*)[68]>(smem_raw);

    const int tid  = threadIdx.x;
    const int warp = tid >> 5, lane = tid & 31;
    const int wm = warp >> 2, wn = warp & 3;    // 2x4 warp grid
    const int gid = lane >> 2, tq = lane & 3;

    const int arow = tid >> 2, ak = (tid & 3) * 8;   // A: 64 t-rows x 32 k
    const int brow = tid >> 3, bh = (tid & 7) * 8;   // B: 32 k-rows x 64 h

    const float* Abase = A + (t0 + arow) * ND + ak;
    const float* Bbase = W + brow * NH + h0 + bh;

    float4 pa[2], pb[2];
#pragma unroll
    for (int i = 0; i < 2; i++) pa[i] = *(const float4*)(Abase + i * 4);
#pragma unroll
    for (int i = 0; i < 2; i++) pb[i] = *(const float4*)(Bbase + i * 4);

    // STS chunk 0 -> buffers 0
    {
        __half2 h2[4];
        h2[0] = __floats2half2_rn(pa[0].x, pa[0].y);
        h2[1] = __floats2half2_rn(pa[0].z, pa[0].w);
        h2[2] = __floats2half2_rn(pa[1].x, pa[1].y);
        h2[3] = __floats2half2_rn(pa[1].z, pa[1].w);
        *reinterpret_cast<uint4*>(AsBuf + arow * 40 + ak) =
            *reinterpret_cast<uint4*>(h2);
        const float* pf = reinterpret_cast<const float*>(pb);
#pragma unroll
        for (int i = 0; i < 8; i++)
            BsBuf[(bh + i) * 34 + brow] = __float2half_rn(pf[i]);
    }
    // load chunk 1 regs
#pragma unroll
    for (int i = 0; i < 2; i++) pa[i] = *(const float4*)(Abase + 32 + i * 4);
#pragma unroll
    for (int i = 0; i < 2; i++) pb[i] = *(const float4*)(Bbase + (size_t)32 * NH + i * 4);

    float acc[2][2][4];
#pragma unroll
    for (int mt = 0; mt < 2; mt++)
#pragma unroll
        for (int nt = 0; nt < 2; nt++)
#pragma unroll
            for (int r = 0; r < 4; r++) acc[mt][nt][r] = 0.f;

#pragma unroll 1
    for (int kc = 0; kc < 16; kc++) {
        __syncthreads();  // chunk kc visible; prior reads of buf[(kc+1)&1] done

        if (kc + 1 < 16) {   // STS chunk kc+1 -> other buffer (overlaps mma)
            __half* as = AsBuf + ((kc + 1) & 1) * 2560;
            __half* bs = BsBuf + ((kc + 1) & 1) * 2176;
            __half2 h2[4];
            h2[0] = __floats2half2_rn(pa[0].x, pa[0].y);
            h2[1] = __floats2half2_rn(pa[0].z, pa[0].w);
            h2[2] = __floats2half2_rn(pa[1].x, pa[1].y);
            h2[3] = __floats2half2_rn(pa[1].z, pa[1].w);
            *reinterpret_cast<uint4*>(as + arow * 40 + ak) =
                *reinterpret_cast<uint4*>(h2);
            const float* pf = reinterpret_cast<const float*>(pb);
#pragma unroll
            for (int i = 0; i < 8; i++)
                bs[(bh + i) * 34 + brow] = __float2half_rn(pf[i]);
        }
        if (kc + 2 < 16) {   // prefetch chunk kc+2 regs (overlaps mma)
            const float* an = Abase + (kc + 2) * 32;
            const float* bn = Bbase + (size_t)(kc + 2) * 32 * NH;
#pragma unroll
            for (int i = 0; i < 2; i++) pa[i] = *(const float4*)(an + i * 4);
#pragma unroll
            for (int i = 0; i < 2; i++) pb[i] = *(const float4*)(bn + i * 4);
        }

        const __half* as = AsBuf + (kc & 1) * 2560;
        const __half* bs = BsBuf + (kc & 1) * 2176;
#pragma unroll
        for (int ks = 0; ks < 2; ks++) {
            const int kb = ks * 16;
            uint32_t af[2][4], bf[2][2];
#pragma unroll
            for (int mt = 0; mt < 2; mt++) {
                const int r = wm * 32 + mt * 16 + gid;
                af[mt][0] = *reinterpret_cast<const uint32_t*>(as + r * 40 + kb + 2 * tq);
                af[mt][1] = *reinterpret_cast<const uint32_t*>(as + (r + 8) * 40 + kb + 2 * tq);
                af[mt][2] = *reinterpret_cast<const uint32_t*>(as + r * 40 + kb + 2 * tq + 8);
                af[mt][3] = *reinterpret_cast<const uint32_t*>(as + (r + 8) * 40 + kb + 2 * tq + 8);
            }
#pragma unroll
            for (int nt = 0; nt < 2; nt++) {
                const int c = wn * 16 + nt * 8 + gid;
                bf[nt][0] = *reinterpret_cast<const uint32_t*>(bs + c * 34 + kb + 2 * tq);
                bf[nt][1] = *reinterpret_cast<const uint32_t*>(bs + c * 34 + kb + 2 * tq + 8);
            }
#pragma unroll
            for (int mt = 0; mt < 2; mt++)
#pragma unroll
                for (int nt = 0; nt < 2; nt++)
                    mma_f16(acc[mt][nt], af[mt], bf[nt]);
        }
    }
    __syncthreads();

    // Transpose via smem: Sout[n(h)][m(t)]
#pragma unroll
    for (int mt = 0; mt < 2; mt++)
#pragma unroll
        for (int nt = 0; nt < 2; nt++) {
            const int n = wn * 16 + nt * 8 + 2 * tq;
            const int m = wm * 32 + mt * 16 + gid;
            Sout[n    ][m    ] = acc[mt][nt][0];
            Sout[n + 1][m    ] = acc[mt][nt][1];
            Sout[n    ][m + 8] = acc[mt][nt][2];
            Sout[n + 1][m + 8] = acc[mt][nt][3];
        }
    __syncthreads();

    // fp16 pack + store: 64 h-rows x 64 t. 256 threads: 16 t per thread.
    {
        const int row = tid >> 2;
        const int cg  = (tid & 3) * 16;
        const float bv = __ldg(&bias[h0 + row]);
        __half2 hx[8];
#pragma unroll
        for (int k = 0; k < 8; k++)
            hx[k] = __floats2half2_rn(Sout[row][cg + 2 * k] + bv,
                                      Sout[row][cg + 2 * k + 1] + bv);
        __half* orow = OutT + (size_t)(h0 + row) * NTX + t0 + cg;
        *reinterpret_cast<uint4*>(orow)     = *reinterpret_cast<uint4*>(hx);
        *reinterpret_cast<uint4*>(orow + 8) = *reinterpret_cast<uint4*>(hx + 4);
    }
}

// ---------------------------------------------------------------------------
// Kernel 2 (R14 best-measured, 32.0 us): fused scores + softmax + cv + LN +
// residual. TYB=8, grid 128, packed fp16 phase 1, depth-8 prefetch.
// ---------------------------------------------------------------------------
__global__ void __launch_bounds__(512, 2)
bahdanau_attn(const float* __restrict__ Ctx, const float* __restrict__ X,
              const float* __restrict__ Va, const float* __restrict__ gamma,
              const float* __restrict__ beta, float* __restrict__ out)
{
    const int b   = blockIdx.x >> 4;
    const int ty0 = (blockIdx.x & 15) * TYB;

    __shared__ __align__(16) __half2 ux2_s[NH * TYB];    // 16 KB: half2(u,u)
    __shared__ __align__(16) __half2 va2_s[NH];          //  2 KB: half2(v,v)
    __shared__ __align__(16) float  part[8 * TYB * NTX]; // 32 KB (cv overlay)
    __shared__ __align__(16) float  attn_s[TYB][NTX];    //  4 KB

    const int tid = threadIdx.x;

    // Stage Ux (one h per thread: 8 ty halfs = uint4) and Va
    {
        uint4 uv = *reinterpret_cast<const uint4*>(
            g_UxT + ((size_t)(b * NH + tid)) * NTY + ty0);
        const __half* up = reinterpret_cast<const __half*>(&uv);
#pragma unroll
        for (int j = 0; j < TYB; j++)
            ux2_s[tid * TYB + j] = __half2half2(up[j]);
        va2_s[tid] = __float2half2_rn(Va[tid]);
    }
    __syncthreads();

    // ---- Phase 1: s[j][tx] = sum_h tanh(Wc[tx,h]+Ux[j,h]) * Va[h]
    {
        const int txp = tid & 63;        // tx pair: tx = 2txp, 2txp+1
        const int g   = tid >> 6;        // h-group: h in [g*64, g*64+64)

        float sacc[TYB][2];
#pragma unroll
        for (int j = 0; j < TYB; j++) { sacc[j][0] = 0.f; sacc[j][1] = 0.f; }

        const __half2* wp = reinterpret_cast<const __half2*>(g_WcT)
                          + (size_t)(b * NH + g * 64) * (NTX / 2) + txp;

        uint32_t wr[8];
#pragma unroll
        for (int i = 0; i < 8; i++)
            wr[i] = __ldg(reinterpret_cast<const uint32_t*>(wp + i * 64));

#pragma unroll 1
        for (int hh = 0; hh < 64; hh += 4) {
            __half2 acc2[TYB];
#pragma unroll
            for (int j = 0; j < TYB; j++)
                acc2[j] = __floats2half2_rn(0.f, 0.f);

#pragma unroll
            for (int i = 0; i < 4; i++) {
                const int h = g * 64 + hh + i;
                const __half2 w2 = *reinterpret_cast<const __half2*>(&wr[i]);
                const __half2 v2 = va2_s[h];
                uint4 ua = *reinterpret_cast<const uint4*>(&ux2_s[h * 8]);
                uint4 ub = *reinterpret_cast<const uint4*>(&ux2_s[h * 8 + 4]);
                const __half2* u = reinterpret_cast<const __half2*>(&ua);
                const __half2* v = reinterpret_cast<const __half2*>(&ub);
#pragma unroll
                for (int j = 0; j < 4; j++)
                    acc2[j] = __hfma2(htanh2(__hadd2(w2, u[j])), v2, acc2[j]);
#pragma unroll
                for (int j = 0; j < 4; j++)
                    acc2[4 + j] = __hfma2(htanh2(__hadd2(w2, v[j])), v2, acc2[4 + j]);
            }
#pragma unroll
            for (int j = 0; j < TYB; j++) {
                float2 f = __half22float2(acc2[j]);
                sacc[j][0] += f.x;
                sacc[j][1] += f.y;
            }
#pragma unroll
            for (int i = 0; i < 4; i++) wr[i] = wr[i + 4];
            if (hh + 8 < 64) {
#pragma unroll
                for (int i = 0; i < 4; i++)
                    wr[4 + i] = __ldg(reinterpret_cast<const uint32_t*>(
                        wp + (hh + 8 + i) * 64));
            }
        }

#pragma unroll
        for (int j = 0; j < TYB; j++)
            *reinterpret_cast<float2*>(&part[(g * TYB + j) * NTX + 2 * txp]) =
                make_float2(sacc[j][0], sacc[j][1]);
    }
    __syncthreads();

    // ---- Phase 2: softmax over tx per ty row; warp j (j<8) handles row j.
    if (tid < 256) {
        const int j = tid >> 5, lane = tid & 31;
        float vals[4];
        float mx = -1e30f;
#pragma unroll
        for (int i = 0; i < 4; i++) {
            int t = lane + i * 32;
            float v = 0.f;
#pragma unroll
            for (int g = 0; g < 8; g++)
                v += part[(g * TYB + j) * NTX + t];
            vals[i] = v;
            mx = fmaxf(mx, v);
        }
#pragma unroll
        for (int off = 16; off; off >>= 1)
            mx = fmaxf(mx, __shfl_xor_sync(0xffffffffu, mx, off));
        float sum = 0.f;
#pragma unroll
        for (int i = 0; i < 4; i++) {
            vals[i] = __expf(vals[i] - mx);
            sum += vals[i];
        }
#pragma unroll
        for (int off = 16; off; off >>= 1)
            sum += __shfl_xor_sync(0xffffffffu, sum, off);
        float inv = __frcp_rn(sum);
#pragma unroll
        for (int i = 0; i < 4; i++)
            attn_s[j][lane + i * 32] = vals[i] * inv;
    }
    __syncthreads();

    // ---- Phase 3: cv[j][d] = sum_tx attn[j][tx] * context[b][tx][d]
    {
        const int g2 = tid >> 8;
        const int l  = tid & 255;
        const int d0 = l * 2;
        float acc[TYB][2];
#pragma unroll
        for (int j = 0; j < TYB; j++) { acc[j][0] = 0.f; acc[j][1] = 0.f; }
        const float* cbase = Ctx + (size_t)b * NTX * ND + (size_t)(g2 * 64) * ND + d0;
#pragma unroll 1
        for (int t = 0; t < 64; t += 8) {
            float2 c[8];
#pragma unroll
            for (int i = 0; i < 8; i++)
                c[i] = *reinterpret_cast<const float2*>(cbase + (size_t)(t + i) * ND);
#pragma unroll
            for (int i = 0; i < 8; i++) {
                const int tt = g2 * 64 + t + i;
#pragma unroll
                for (int j = 0; j < TYB; j++) {
                    float a = attn_s[j][tt];
                    acc[j][0] += a * c[i].x;
                    acc[j][1] += a * c[i].y;
                }
            }
        }
#pragma unroll
        for (int j = 0; j < TYB; j++) {
            part[g2 * 4096 + j * 512 + d0]     = acc[j][0];  // cvp overlay
            part[g2 * 4096 + j * 512 + d0 + 1] = acc[j][1];
        }
    }
    __syncthreads();

    // ---- Phase 4: LayerNorm + residual. Warp j (j<8) handles row j.
    if (tid < 256) {
        const int j = tid >> 5, lane = tid & 31;
        float vals[16];
        float sum = 0.f;
#pragma unroll
        for (int i = 0; i < 16; i++) {
            int d = i * 32 + lane;
            vals[i] = part[j * 512 + d] + part[4096 + j * 512 + d];
            sum += vals[i];
        }
#pragma unroll
        for (int off = 16; off; off >>= 1)
            sum += __shfl_xor_sync(0xffffffffu, sum, off);
        const float mean = sum * (1.0f / ND);
        float vsum = 0.f;
#pragma unroll
        for (int i = 0; i < 16; i++) {
            float dlt = vals[i] - mean;
            vsum += dlt * dlt;
        }
#pragma unroll
        for (int off = 16; off; off >>= 1)
            vsum += __shfl_xor_sync(0xffffffffu, vsum, off);
        const float scale = rsqrtf(vsum * (1.0f / ND) + 1e-3f);

        const int ty = ty0 + j;
        const float* xr = X + ((size_t)b * NTY + ty) * ND;
        float* orow = out + ((size_t)b * NTY + ty) * ND;
#pragma unroll
        for (int i = 0; i < 16; i++) {
            int d = i * 32 + lane;
            orow[d] = (vals[i] - mean) * scale * gamma[d] + beta[d] + xr[d];
        }
    }
}

// ---------------------------------------------------------------------------
extern "C" void kernel_launch(void* const* d_in, const int* in_sizes, int n_in,
                              void* d_out, int out_size)
{
    const float* ctx   = (const float*)d_in[0];
    const float* x     = (const float*)d_in[1];
    const float* Wa    = (const float*)d_in[2];
    const float* bWa   = (const float*)d_in[3];
    const float* Ua    = (const float*)d_in[4];
    const float* bUa   = (const float*)d_in[5];
    const float* Va    = (const float*)d_in[6];
    // d_in[7] = bVa: scalar added to scores; cancels exactly in softmax.
    const float* gamma = (const float*)d_in[8];
    const float* beta  = (const float*)d_in[9];
    float* out = (float*)d_out;

    dim3 g1(NH / 64, NTX / 64, NB * 2);   // (8, 2, 16) = 256 blocks
    bahdanau_gemm_tc<<<g1, 256>>>(ctx, x, Wa, bWa, Ua, bUa);

    bahdanau_attn<<<NB * (NTY / TYB), 512>>>(ctx, x, Va, gamma, beta, out);
}